// round 13
// baseline (speedup 1.0000x reference)
#include <cuda_runtime.h>
#include <cuda_bf16.h>
#include <cstddef>
#include <cstdint>

// Problem dims
#define B_    256
#define T_    100
#define IN_   128
#define H_    1024
#define OUT_  35
#define TB_   (B_ * T_)   // 25600 rows of the batched GEMMs

// ---------------- scratch (device globals; no allocation allowed) ----------
__device__ __align__(128) float   g_xs[(size_t)TB_ * IN_];   // [T,B,IN]/15 fp32
__device__ __align__(128) float   g_q1[H_ * IN_];            // layer-1 fp32 quant weights
__device__ __align__(128) int8_t  g_w2k[H_ * H_];
__device__ __align__(128) int8_t  g_w2e[H_ * H_];
__device__ __align__(128) int8_t  g_w3k[H_ * H_];
__device__ __align__(128) int8_t  g_w3e[H_ * H_];
__device__ __align__(128) int8_t  g_w4k[128 * H_];           // rows 35..127 zero
__device__ __align__(128) int8_t  g_w4e[128 * H_];
__device__ __align__(128) float   g_cur[(size_t)TB_ * H_];   // combined currents
__device__ __align__(128) int8_t  g_spk8[(size_t)TB_ * H_];  // spikes as s8 (exact)
__device__ __align__(128) float   g_R[TB_];

#define ESCALE 4.656612873077393e-10f   // 2^-31

// ---------------- PTX helpers ----------------------------------------------
__device__ __forceinline__ uint32_t smem_u32(const void* p) {
    uint32_t a;
    asm("{ .reg .u64 t; cvta.to.shared.u64 t, %1; cvt.u32.u64 %0, t; }" : "=r"(a) : "l"(p));
    return a;
}
__device__ __forceinline__ void cp16(uint32_t s, const void* g) {
    asm volatile("cp.async.cg.shared.global [%0], [%1], 16;" :: "r"(s), "l"(g));
}
__device__ __forceinline__ void cp_commit() {
    asm volatile("cp.async.commit_group;" ::: "memory");
}
__device__ __forceinline__ void ldsm4(uint32_t& r0, uint32_t& r1, uint32_t& r2, uint32_t& r3,
                                      uint32_t a) {
    asm volatile("ldmatrix.sync.aligned.m8n8.x4.shared.b16 {%0,%1,%2,%3}, [%4];"
                 : "=r"(r0), "=r"(r1), "=r"(r2), "=r"(r3) : "r"(a));
}
__device__ __forceinline__ void mma_s8(int* d, const uint32_t* a, const uint32_t* b) {
    asm volatile("mma.sync.aligned.m16n8k32.row.col.s32.s8.s8.s32 "
                 "{%0,%1,%2,%3}, {%4,%5,%6,%7}, {%8,%9}, {%0,%1,%2,%3};"
                 : "+r"(d[0]), "+r"(d[1]), "+r"(d[2]), "+r"(d[3])
                 : "r"(a[0]), "r"(a[1]), "r"(a[2]), "r"(a[3]), "r"(b[0]), "r"(b[1]));
}

// ---------------- fused dual-B s8 IMMA GEMM (spike layers) -----------------
// C[M, Nstr] tile = scale * (A @ Bk^T) + escale * (A @ Be^T); all exact ints.
// BM=128, BN=128, BK=128 s8 (128B swizzled rows). 512 threads = 16 warps,
// warp grid 2(m) x 8(n), warp tile 64x16 per accumulator set.
__global__ __launch_bounds__(512)
void gemm_dual_s8(const int8_t* __restrict__ A,
                  const int8_t* __restrict__ Bk,
                  const int8_t* __restrict__ Be,
                  float* __restrict__ C, int Nstr, int K, float scale, float escale) {
    constexpr int STAGE = 3 * 16384;
    extern __shared__ __align__(1024) char smem[];
    const int tid = threadIdx.x;
    const int wid = tid >> 5, lid = tid & 31;
    const int row0 = blockIdx.y * 128, col0 = blockIdx.x * 128;
    const int wm = wid & 1, wn = wid >> 1;
    const int warpM0 = wm * 64;
    const int warpN0 = wn * 16;
    const uint32_t sb = smem_u32(smem);
    const int NCH = K / 128;

    int acc1[4][2][4], acc2[4][2][4];
#pragma unroll
    for (int i = 0; i < 4; i++)
#pragma unroll
        for (int j = 0; j < 2; j++)
#pragma unroll
            for (int c = 0; c < 4; c++) { acc1[i][j][c] = 0; acc2[i][j][c] = 0; }

    auto issue = [&](int i) {
        const int k0 = i * 128;
        const uint32_t base = sb + (i & 1) * STAGE;
#pragma unroll
        for (int p = 0; p < 2; p++) {
            int u = tid + p * 512;
            int r = u >> 3, c = u & 7;
            uint32_t sw = r * 128 + ((c ^ (r & 7)) << 4);
            cp16(base + sw,         A  + (size_t)(row0 + r) * K + k0 + c * 16);
            cp16(base + 16384 + sw, Bk + (size_t)(col0 + r) * K + k0 + c * 16);
            cp16(base + 32768 + sw, Be + (size_t)(col0 + r) * K + k0 + c * 16);
        }
        cp_commit();
    };

    issue(0);
    if (NCH > 1) issue(1);

    for (int i = 0; i < NCH; i++) {
        const uint32_t base = sb + (i & 1) * STAGE;
        if (i + 1 < NCH) asm volatile("cp.async.wait_group 1;" ::: "memory");
        else             asm volatile("cp.async.wait_group 0;" ::: "memory");
        __syncthreads();

#pragma unroll
        for (int j = 0; j < 4; j++) {        // 4 k32 steps per 128-byte chunk
            uint32_t a[4][4], bk[2][2], be[2][2];
#pragma unroll
            for (int mf = 0; mf < 4; mf++) {
                int r = warpM0 + mf * 16 + (lid & 15);
                int c = 2 * j + (lid >> 4);            // 16B segment index
                ldsm4(a[mf][0], a[mf][1], a[mf][2], a[mf][3],
                      base + r * 128 + ((c ^ (r & 7)) << 4));
            }
            {
                int r = warpN0 + (lid & 7) + (((lid >> 4) & 1) << 3);
                int c = 2 * j + ((lid >> 3) & 1);
                uint32_t sw = r * 128 + ((c ^ (r & 7)) << 4);
                uint32_t t0, t1, t2, t3;
                ldsm4(t0, t1, t2, t3, base + 16384 + sw);
                bk[0][0] = t0; bk[0][1] = t1; bk[1][0] = t2; bk[1][1] = t3;
                ldsm4(t0, t1, t2, t3, base + 32768 + sw);
                be[0][0] = t0; be[0][1] = t1; be[1][0] = t2; be[1][1] = t3;
            }
#pragma unroll
            for (int mf = 0; mf < 4; mf++)
#pragma unroll
                for (int nf = 0; nf < 2; nf++) {
                    mma_s8(acc1[mf][nf], a[mf], bk[nf]);
                    mma_s8(acc2[mf][nf], a[mf], be[nf]);
                }
        }
        __syncthreads();
        if (i + 2 < NCH) issue(i + 2);
    }

    // epilogue: C = scale*acc1 + escale*acc2 (int->float exact, < 2^24)
#pragma unroll
    for (int mf = 0; mf < 4; mf++) {
        int r = row0 + warpM0 + mf * 16 + (lid >> 2);
#pragma unroll
        for (int nf = 0; nf < 2; nf++) {
            int cc = col0 + warpN0 + nf * 8 + (lid & 3) * 2;
            float2 v0 = {fmaf(scale, __int2float_rn(acc1[mf][nf][0]),
                              escale * __int2float_rn(acc2[mf][nf][0])),
                         fmaf(scale, __int2float_rn(acc1[mf][nf][1]),
                              escale * __int2float_rn(acc2[mf][nf][1]))};
            float2 v1 = {fmaf(scale, __int2float_rn(acc1[mf][nf][2]),
                              escale * __int2float_rn(acc2[mf][nf][2])),
                         fmaf(scale, __int2float_rn(acc1[mf][nf][3]),
                              escale * __int2float_rn(acc2[mf][nf][3]))};
            *(float2*)&C[(size_t)r * Nstr + cc]       = v0;
            *(float2*)&C[(size_t)(r + 8) * Nstr + cc] = v1;
        }
    }
}

// ---------------- fp32 SGEMM for layer 1 (R6-proven, 0 spike flips) --------
#define BM 128
#define BN1 128
#define BK 16
__global__ __launch_bounds__(256)
void gemm_nt_kernel(const float* __restrict__ A, const float* __restrict__ W,
                    float* __restrict__ C, int M, int N, int K) {
    __shared__ float As[BK][BM];
    __shared__ float Ws[BK][BN1];
    const int tid  = threadIdx.x;
    const int tr   = tid >> 4;
    const int tc   = tid & 15;
    const int row0 = blockIdx.y * BM;
    const int col0 = blockIdx.x * BN1;

    float acc[8][8];
#pragma unroll
    for (int i = 0; i < 8; i++)
#pragma unroll
        for (int j = 0; j < 8; j++) acc[i][j] = 0.0f;

    for (int k0 = 0; k0 < K; k0 += BK) {
#pragma unroll
        for (int l = 0; l < 2; l++) {
            int lin = tid + l * 256;
            int r = lin >> 2, c4 = (lin & 3) << 2;
            float4 v = *(const float4*)&A[(size_t)(row0 + r) * K + k0 + c4];
            As[c4 + 0][r] = v.x; As[c4 + 1][r] = v.y;
            As[c4 + 2][r] = v.z; As[c4 + 3][r] = v.w;
        }
#pragma unroll
        for (int l = 0; l < 2; l++) {
            int lin = tid + l * 256;
            int r = lin >> 2, c4 = (lin & 3) << 2;
            float4 v = *(const float4*)&W[(size_t)(col0 + r) * K + k0 + c4];
            Ws[c4 + 0][r] = v.x; Ws[c4 + 1][r] = v.y;
            Ws[c4 + 2][r] = v.z; Ws[c4 + 3][r] = v.w;
        }
        __syncthreads();
#pragma unroll
        for (int k = 0; k < BK; k++) {
            float4 a0 = *(const float4*)&As[k][tr * 8];
            float4 a1 = *(const float4*)&As[k][tr * 8 + 4];
            float4 b0 = *(const float4*)&Ws[k][tc * 8];
            float4 b1 = *(const float4*)&Ws[k][tc * 8 + 4];
            float a[8] = {a0.x, a0.y, a0.z, a0.w, a1.x, a1.y, a1.z, a1.w};
            float b[8] = {b0.x, b0.y, b0.z, b0.w, b1.x, b1.y, b1.z, b1.w};
#pragma unroll
            for (int i = 0; i < 8; i++)
#pragma unroll
                for (int j = 0; j < 8; j++)
                    acc[i][j] = fmaf(a[i], b[j], acc[i][j]);
        }
        __syncthreads();
    }
#pragma unroll
    for (int i = 0; i < 8; i++) {
        int row = row0 + tr * 8 + i;
#pragma unroll
        for (int j = 0; j < 8; j++)
            C[(size_t)row * N + col0 + tc * 8 + j] = acc[i][j];
    }
}

// ---------------- quant kernels --------------------------------------------
__global__ void quant_kernel(const float* __restrict__ w, float* __restrict__ q,
                             int n, float wmin, float wmax, float scale) {
    int i = blockIdx.x * blockDim.x + threadIdx.x;
    if (i >= n) return;
    float wc = fminf(fmaxf(w[i], wmin), wmax);
    float t  = __fdiv_rn(__fsub_rn(wc, wmin), scale);
    q[i] = __fadd_rn(__fmul_rn(rintf(t), scale), wmin);
}

// k index (s8 exact) + e8 = rint((q - wmin - k*scale) * 2^31), double precision.
__global__ void quantke8_kernel(const float* __restrict__ w,
                                int8_t* __restrict__ kq, int8_t* __restrict__ eq,
                                int n, int nsrc, float wmin, float wmax, float scale) {
    int i = blockIdx.x * blockDim.x + threadIdx.x;
    if (i >= n) return;
    int k8 = 0, e8 = 0;
    if (i < nsrc) {
        float wc = fminf(fmaxf(w[i], wmin), wmax);
        float kf = rintf(__fdiv_rn(__fsub_rn(wc, wmin), scale));
        float q = __fadd_rn(__fmul_rn(kf, scale), wmin);
        double ed = ((double)q - (double)wmin - (double)scale * (double)kf) * 2147483648.0;
        int ei = (int)rint(ed);
        e8 = ei > 127 ? 127 : (ei < -127 ? -127 : ei);
        k8 = (int)kf;
    }
    kq[i] = (int8_t)k8;
    eq[i] = (int8_t)e8;
}

// ---------------- x: [B,T,IN] -> [T,B,IN]/15 (fp32, R6-identical) ----------
__global__ void prep_x_kernel(const float* __restrict__ x, float* __restrict__ xs) {
    int idx = blockIdx.x * blockDim.x + threadIdx.x;
    if (idx >= TB_ * IN_) return;
    int i  = idx % IN_;
    int rb = idx / IN_;
    int b  = rb % B_;
    int t  = rb / B_;
    xs[idx] = __fdiv_rn(x[((size_t)b * T_ + t) * IN_ + i], 15.0f);
}

// ---------------- rowsum of s8 spikes (exact via dp4a) ---------------------
__global__ void rowsum8_kernel(const int8_t* __restrict__ S, float* __restrict__ R) {
    int w = (blockIdx.x * blockDim.x + threadIdx.x) >> 5;
    int l = threadIdx.x & 31;
    if (w >= TB_) return;
    const int4* p = (const int4*)(S + (size_t)w * H_);
    int s = 0;
#pragma unroll
    for (int i = 0; i < 2; i++) {
        int4 v = p[l + i * 32];
        s = __dp4a(v.x, 0x01010101, s);
        s = __dp4a(v.y, 0x01010101, s);
        s = __dp4a(v.z, 0x01010101, s);
        s = __dp4a(v.w, 0x01010101, s);
    }
#pragma unroll
    for (int o = 16; o; o >>= 1) s += __shfl_xor_sync(0xffffffffu, s, o);
    if (l == 0) R[w] = (float)s;
}

// ---------------- LIF scans ------------------------------------------------
// Layer 1: direct fp32 currents (R6-identical math)
__global__ void lif_sub1_kernel(const float* __restrict__ cur, float* __restrict__ spk,
                                int8_t* __restrict__ spk8, float beta, int n) {
    int idx = blockIdx.x * blockDim.x + threadIdx.x;
    if (idx >= n) return;
    float m = 0.0f;
    for (int t = 0; t < T_; t++) {
        float c     = cur[(size_t)t * n + idx];
        float reset = (m > 1.0f) ? 1.0f : 0.0f;
        float base  = __fadd_rn(__fmul_rn(beta, m), c);
        m = base - reset;
        float s = (m > 1.0f) ? 1.0f : 0.0f;
        spk[(size_t)t * n + idx]  = s;
        spk8[(size_t)t * n + idx] = (int8_t)(m > 1.0f ? 1 : 0);
    }
}

// Hidden layers: c = D + wmin*R (D already combined in the GEMM epilogue)
__global__ void lif_sub_kernel(const float* __restrict__ D, const float* __restrict__ R,
                               float* __restrict__ spk, int8_t* __restrict__ spk8,
                               float beta, float wmin) {
    int idx = blockIdx.x * blockDim.x + threadIdx.x;
    if (idx >= B_ * H_) return;
    int b = idx / H_, h = idx % H_;
    float m = 0.0f;
    for (int t = 0; t < T_; t++) {
        size_t mm = (size_t)t * B_ + b;
        float c = fmaf(wmin, R[mm], D[mm * H_ + h]);
        float reset = (m > 1.0f) ? 1.0f : 0.0f;
        float base  = __fadd_rn(__fmul_rn(beta, m), c);
        m = base - reset;
        float s = (m > 1.0f) ? 1.0f : 0.0f;
        spk[(size_t)t * (B_ * H_) + idx]  = s;
        spk8[(size_t)t * (B_ * H_) + idx] = (int8_t)(m > 1.0f ? 1 : 0);
    }
}

__global__ void lif_zero_kernel(const float* __restrict__ D, const float* __restrict__ R,
                                float* __restrict__ spk, float* __restrict__ mem,
                                float beta, float wmin) {
    int idx = blockIdx.x * blockDim.x + threadIdx.x;
    if (idx >= B_ * OUT_) return;
    int b = idx / OUT_, h = idx % OUT_;
    float m = 0.0f;
    for (int t = 0; t < T_; t++) {
        size_t mm = (size_t)t * B_ + b;
        float c = fmaf(wmin, R[mm], D[mm * 128 + h]);
        bool  rst  = (m > 1.0f);
        float base = __fadd_rn(__fmul_rn(beta, m), c);
        m = rst ? 0.0f : base;
        spk[(size_t)t * (B_ * OUT_) + idx] = (m > 1.0f) ? 1.0f : 0.0f;
        mem[(size_t)t * (B_ * OUT_) + idx] = m;
    }
}

// ---------------------------------------------------------------------------
extern "C" void kernel_launch(void* const* d_in, const int* in_sizes, int n_in,
                              void* d_out, int out_size) {
    const float* x  = (const float*)d_in[0];
    const float* w1 = (const float*)d_in[1];
    const float* w2 = (const float*)d_in[2];
    const float* w3 = (const float*)d_in[3];
    const float* w4 = (const float*)d_in[4];
    float* out = (float*)d_out;

    float *xs, *q1, *cur, *R;
    int8_t *w2k, *w2e, *w3k, *w3e, *w4k, *w4e, *spk8;
    cudaGetSymbolAddress((void**)&xs, g_xs);   cudaGetSymbolAddress((void**)&q1, g_q1);
    cudaGetSymbolAddress((void**)&w2k, g_w2k); cudaGetSymbolAddress((void**)&w2e, g_w2e);
    cudaGetSymbolAddress((void**)&w3k, g_w3k); cudaGetSymbolAddress((void**)&w3e, g_w3e);
    cudaGetSymbolAddress((void**)&w4k, g_w4k); cudaGetSymbolAddress((void**)&w4e, g_w4e);
    cudaGetSymbolAddress((void**)&cur, g_cur);
    cudaGetSymbolAddress((void**)&spk8, g_spk8);
    cudaGetSymbolAddress((void**)&R, g_R);

    const size_t SPK  = (size_t)TB_ * H_;
    const size_t SPK4 = (size_t)TB_ * OUT_;
    float* spk1 = out;
    float* spk2 = out + SPK;
    float* spk3 = out + 2 * SPK;
    float* spk4 = out + 3 * SPK;
    float* mem4 = out + 3 * SPK + SPK4;

    const float scale1 = (float)((0.5 - (-0.5)) / 15.0);
    const float scale2 = (float)((1.0 - 0.001) / 15.0);

    const int SMEM = 2 * 3 * 16384;   // 98304
    cudaFuncSetAttribute(gemm_dual_s8, cudaFuncAttributeMaxDynamicSharedMemorySize, SMEM);

    // ---- prep
    quant_kernel<<<(H_ * IN_ + 255) / 256, 256>>>(w1, q1, H_ * IN_, -0.5f, 0.5f, scale1);
    quantke8_kernel<<<(H_ * H_ + 255) / 256, 256>>>(w2, w2k, w2e, H_ * H_, H_ * H_, 0.001f, 1.0f, scale2);
    quantke8_kernel<<<(H_ * H_ + 255) / 256, 256>>>(w3, w3k, w3e, H_ * H_, H_ * H_, 0.001f, 1.0f, scale2);
    quantke8_kernel<<<(128 * H_ + 255) / 256, 256>>>(w4, w4k, w4e, 128 * H_, OUT_ * H_, 0.001f, 1.0f, scale2);
    prep_x_kernel<<<(TB_ * IN_ + 255) / 256, 256>>>(x, xs);

    dim3 gHid(H_ / 128, TB_ / 128);   // (8, 200)
    dim3 gOut(1, TB_ / 128);          // (1, 200)
    const int RS_BLK = (TB_ * 32 + 255) / 256;

    // ---- Layer 1 (fp32, R6-proven path)
    gemm_nt_kernel<<<gHid, 256>>>(xs, q1, cur, TB_, H_, IN_);
    lif_sub1_kernel<<<(B_ * H_ + 255) / 256, 256>>>(cur, spk1, spk8, 0.9f, B_ * H_);

    // ---- Layer 2 (fused k+e dual s8 GEMM, exact integers)
    rowsum8_kernel<<<RS_BLK, 256>>>(spk8, R);
    gemm_dual_s8<<<gHid, 512, SMEM>>>(spk8, w2k, w2e, cur, H_, H_, scale2, ESCALE);
    lif_sub_kernel<<<(B_ * H_ + 255) / 256, 256>>>(cur, R, spk2, spk8, 0.85f, 0.001f);

    // ---- Layer 3
    rowsum8_kernel<<<RS_BLK, 256>>>(spk8, R);
    gemm_dual_s8<<<gHid, 512, SMEM>>>(spk8, w3k, w3e, cur, H_, H_, scale2, ESCALE);
    lif_sub_kernel<<<(B_ * H_ + 255) / 256, 256>>>(cur, R, spk3, spk8, 0.8f, 0.001f);

    // ---- Layer 4 (N padded to 128)
    rowsum8_kernel<<<RS_BLK, 256>>>(spk8, R);
    gemm_dual_s8<<<gOut, 512, SMEM>>>(spk8, w4k, w4e, cur, 128, H_, scale2, ESCALE);
    lif_zero_kernel<<<(B_ * OUT_ + 255) / 256, 256>>>(cur, R, spk4, mem4, 0.95f, 0.001f);

    (void)in_sizes; (void)n_in; (void)out_size;
}

// round 16
// speedup vs baseline: 2.1606x; 2.1606x over previous
#include <cuda_runtime.h>
#include <cuda_bf16.h>
#include <cstddef>
#include <cstdint>

// Problem dims
#define B_    256
#define T_    100
#define IN_   128
#define H_    1024
#define OUT_  35
#define TB_   (B_ * T_)   // 25600 rows of the batched GEMMs

// ---------------- scratch (device globals; no allocation allowed) ----------
__device__ __align__(128) float         g_xs[(size_t)TB_ * IN_];   // [T,B,IN]/15 fp32
__device__ __align__(128) float         g_q1[H_ * IN_];            // layer-1 fp32 quant weights
__device__ __align__(128) __nv_bfloat16 g_w2k[H_ * H_];
__device__ __align__(128) __nv_bfloat16 g_w2e[H_ * H_];
__device__ __align__(128) __nv_bfloat16 g_w3k[H_ * H_];
__device__ __align__(128) __nv_bfloat16 g_w3e[H_ * H_];
__device__ __align__(128) __nv_bfloat16 g_w4k[128 * H_];           // rows 35..127 zero
__device__ __align__(128) __nv_bfloat16 g_w4e[128 * H_];
__device__ __align__(128) float         g_cur[(size_t)TB_ * H_];   // combined currents
__device__ __align__(128) __nv_bfloat16 g_spkb[(size_t)TB_ * H_];  // spikes bf16 (exact)
__device__ __align__(128) float         g_R[TB_];

// ---------------- PTX helpers ----------------------------------------------
__device__ __forceinline__ uint32_t smem_u32(const void* p) {
    uint32_t a;
    asm("{ .reg .u64 t; cvta.to.shared.u64 t, %1; cvt.u32.u64 %0, t; }" : "=r"(a) : "l"(p));
    return a;
}
__device__ __forceinline__ void cp16(uint32_t s, const void* g) {
    asm volatile("cp.async.cg.shared.global [%0], [%1], 16;" :: "r"(s), "l"(g));
}
__device__ __forceinline__ void cp_commit() {
    asm volatile("cp.async.commit_group;" ::: "memory");
}
__device__ __forceinline__ void ldsm4(uint32_t& r0, uint32_t& r1, uint32_t& r2, uint32_t& r3,
                                      uint32_t a) {
    asm volatile("ldmatrix.sync.aligned.m8n8.x4.shared.b16 {%0,%1,%2,%3}, [%4];"
                 : "=r"(r0), "=r"(r1), "=r"(r2), "=r"(r3) : "r"(a));
}
__device__ __forceinline__ void mma16816(float* d, const uint32_t* a, const uint32_t* b) {
    asm volatile("mma.sync.aligned.m16n8k16.row.col.f32.bf16.bf16.f32 "
                 "{%0,%1,%2,%3}, {%4,%5,%6,%7}, {%8,%9}, {%0,%1,%2,%3};"
                 : "+f"(d[0]), "+f"(d[1]), "+f"(d[2]), "+f"(d[3])
                 : "r"(a[0]), "r"(a[1]), "r"(a[2]), "r"(a[3]), "r"(b[0]), "r"(b[1]));
}

// ---------------- fused dual-B HMMA GEMM (spike layers) --------------------
// C[M, Nstr] tile = scale * (A @ Bk^T) + (A @ Be^T)
// BM=128, BN=64, BK=64 (128B swizzled rows). 256 threads = 8 warps,
// warp grid 2(m) x 4(n), warp tile 64x16 per accumulator set.
// 3-stage cp.async pipeline, 2 CTAs/SM for latency hiding.
// Same mma ops in same k-order as R8 => bit-identical results.
__global__ __launch_bounds__(256, 2)
void gemm_dual(const __nv_bfloat16* __restrict__ A,
               const __nv_bfloat16* __restrict__ Bk,
               const __nv_bfloat16* __restrict__ Be,
               float* __restrict__ C, int Nstr, int K, float scale) {
    constexpr int ABYTES = 128 * 128;          // 16384
    constexpr int BBYTES = 64 * 128;           // 8192
    constexpr int STAGE  = ABYTES + 2 * BBYTES;// 32768
    extern __shared__ __align__(1024) char smem[];
    const int tid = threadIdx.x;
    const int wid = tid >> 5, lid = tid & 31;
    const int row0 = blockIdx.y * 128, col0 = blockIdx.x * 64;
    const int wm = wid & 1, wn = wid >> 1;     // 2 x 4 warp grid
    const int warpM0 = wm * 64;
    const int warpN0 = wn * 16;
    const uint32_t sb = smem_u32(smem);
    const int NCH = K / 64;

    float acc1[4][2][4], acc2[4][2][4];
#pragma unroll
    for (int i = 0; i < 4; i++)
#pragma unroll
        for (int j = 0; j < 2; j++)
#pragma unroll
            for (int c = 0; c < 4; c++) { acc1[i][j][c] = 0.0f; acc2[i][j][c] = 0.0f; }

    auto issue = [&](int i) {
        const int k0 = i * 64;
        const uint32_t base = sb + (i % 3) * STAGE;
        // A tile: 128 rows x 128B = 1024 packets (4 per thread)
#pragma unroll
        for (int p = 0; p < 4; p++) {
            int u = tid + p * 256;
            int r = u >> 3, c = u & 7;
            uint32_t sw = r * 128 + ((c ^ (r & 7)) << 4);
            cp16(base + sw, A + (size_t)(row0 + r) * K + k0 + c * 8);
        }
        // Bk, Be tiles: 64 rows x 128B = 512 packets each (2 per thread)
#pragma unroll
        for (int p = 0; p < 2; p++) {
            int u = tid + p * 256;
            int r = u >> 3, c = u & 7;
            uint32_t sw = r * 128 + ((c ^ (r & 7)) << 4);
            cp16(base + ABYTES + sw,          Bk + (size_t)(col0 + r) * K + k0 + c * 8);
            cp16(base + ABYTES + BBYTES + sw, Be + (size_t)(col0 + r) * K + k0 + c * 8);
        }
        cp_commit();
    };

    issue(0);
    if (NCH > 1) issue(1);
    if (NCH > 2) issue(2);

    for (int i = 0; i < NCH; i++) {
        const uint32_t base = sb + (i % 3) * STAGE;
        if (i + 1 < NCH) {
            if (i + 2 < NCH) asm volatile("cp.async.wait_group 2;" ::: "memory");
            else             asm volatile("cp.async.wait_group 1;" ::: "memory");
        } else {
            asm volatile("cp.async.wait_group 0;" ::: "memory");
        }
        __syncthreads();

#pragma unroll
        for (int j = 0; j < 4; j++) {
            uint32_t a[4][4], bk[2][2], be[2][2];
#pragma unroll
            for (int mf = 0; mf < 4; mf++) {
                int r = warpM0 + mf * 16 + (lid & 15);
                int c = 2 * j + (lid >> 4);
                ldsm4(a[mf][0], a[mf][1], a[mf][2], a[mf][3],
                      base + r * 128 + ((c ^ (r & 7)) << 4));
            }
            {
                int r = warpN0 + (lid & 7) + (((lid >> 4) & 1) << 3);
                int c = 2 * j + ((lid >> 3) & 1);
                uint32_t sw = r * 128 + ((c ^ (r & 7)) << 4);
                uint32_t t0, t1, t2, t3;
                ldsm4(t0, t1, t2, t3, base + ABYTES + sw);
                bk[0][0] = t0; bk[0][1] = t1; bk[1][0] = t2; bk[1][1] = t3;
                ldsm4(t0, t1, t2, t3, base + ABYTES + BBYTES + sw);
                be[0][0] = t0; be[0][1] = t1; be[1][0] = t2; be[1][1] = t3;
            }
#pragma unroll
            for (int mf = 0; mf < 4; mf++)
#pragma unroll
                for (int nf = 0; nf < 2; nf++) {
                    mma16816(acc1[mf][nf], a[mf], bk[nf]);
                    mma16816(acc2[mf][nf], a[mf], be[nf]);
                }
        }
        __syncthreads();
        if (i + 3 < NCH) issue(i + 3);
    }

    // epilogue: C = scale*acc1 + acc2
#pragma unroll
    for (int mf = 0; mf < 4; mf++) {
        int r = row0 + warpM0 + mf * 16 + (lid >> 2);
#pragma unroll
        for (int nf = 0; nf < 2; nf++) {
            int cc = col0 + warpN0 + nf * 8 + (lid & 3) * 2;
            float2 v0 = {fmaf(scale, acc1[mf][nf][0], acc2[mf][nf][0]),
                         fmaf(scale, acc1[mf][nf][1], acc2[mf][nf][1])};
            float2 v1 = {fmaf(scale, acc1[mf][nf][2], acc2[mf][nf][2]),
                         fmaf(scale, acc1[mf][nf][3], acc2[mf][nf][3])};
            *(float2*)&C[(size_t)r * Nstr + cc]       = v0;
            *(float2*)&C[(size_t)(r + 8) * Nstr + cc] = v1;
        }
    }
}

// ---------------- fp32 SGEMM for layer 1 (R6-proven, 0 spike flips) --------
#define BM 128
#define BN1 128
#define BK 16
__global__ __launch_bounds__(256)
void gemm_nt_kernel(const float* __restrict__ A, const float* __restrict__ W,
                    float* __restrict__ C, int M, int N, int K) {
    __shared__ float As[BK][BM];
    __shared__ float Ws[BK][BN1];
    const int tid  = threadIdx.x;
    const int tr   = tid >> 4;
    const int tc   = tid & 15;
    const int row0 = blockIdx.y * BM;
    const int col0 = blockIdx.x * BN1;

    float acc[8][8];
#pragma unroll
    for (int i = 0; i < 8; i++)
#pragma unroll
        for (int j = 0; j < 8; j++) acc[i][j] = 0.0f;

    for (int k0 = 0; k0 < K; k0 += BK) {
#pragma unroll
        for (int l = 0; l < 2; l++) {
            int lin = tid + l * 256;
            int r = lin >> 2, c4 = (lin & 3) << 2;
            float4 v = *(const float4*)&A[(size_t)(row0 + r) * K + k0 + c4];
            As[c4 + 0][r] = v.x; As[c4 + 1][r] = v.y;
            As[c4 + 2][r] = v.z; As[c4 + 3][r] = v.w;
        }
#pragma unroll
        for (int l = 0; l < 2; l++) {
            int lin = tid + l * 256;
            int r = lin >> 2, c4 = (lin & 3) << 2;
            float4 v = *(const float4*)&W[(size_t)(col0 + r) * K + k0 + c4];
            Ws[c4 + 0][r] = v.x; Ws[c4 + 1][r] = v.y;
            Ws[c4 + 2][r] = v.z; Ws[c4 + 3][r] = v.w;
        }
        __syncthreads();
#pragma unroll
        for (int k = 0; k < BK; k++) {
            float4 a0 = *(const float4*)&As[k][tr * 8];
            float4 a1 = *(const float4*)&As[k][tr * 8 + 4];
            float4 b0 = *(const float4*)&Ws[k][tc * 8];
            float4 b1 = *(const float4*)&Ws[k][tc * 8 + 4];
            float a[8] = {a0.x, a0.y, a0.z, a0.w, a1.x, a1.y, a1.z, a1.w};
            float b[8] = {b0.x, b0.y, b0.z, b0.w, b1.x, b1.y, b1.z, b1.w};
#pragma unroll
            for (int i = 0; i < 8; i++)
#pragma unroll
                for (int j = 0; j < 8; j++)
                    acc[i][j] = fmaf(a[i], b[j], acc[i][j]);
        }
        __syncthreads();
    }
#pragma unroll
    for (int i = 0; i < 8; i++) {
        int row = row0 + tr * 8 + i;
#pragma unroll
        for (int j = 0; j < 8; j++)
            C[(size_t)row * N + col0 + tc * 8 + j] = acc[i][j];
    }
}

// ---------------- quant kernels --------------------------------------------
__global__ void quant_kernel(const float* __restrict__ w, float* __restrict__ q,
                             int n, float wmin, float wmax, float scale) {
    int i = blockIdx.x * blockDim.x + threadIdx.x;
    if (i >= n) return;
    float wc = fminf(fmaxf(w[i], wmin), wmax);
    float t  = __fdiv_rn(__fsub_rn(wc, wmin), scale);
    q[i] = __fadd_rn(__fmul_rn(rintf(t), scale), wmin);
}

// k index (bf16 exact) + e = q - (wmin + k*scale) in DOUBLE, then bf16 (R8).
__global__ void quantke_kernel(const float* __restrict__ w,
                               __nv_bfloat16* __restrict__ kq, __nv_bfloat16* __restrict__ eq,
                               int n, int nsrc, float wmin, float wmax, float scale) {
    int i = blockIdx.x * blockDim.x + threadIdx.x;
    if (i >= n) return;
    float kf = 0.0f, e = 0.0f;
    if (i < nsrc) {
        float wc = fminf(fmaxf(w[i], wmin), wmax);
        kf = rintf(__fdiv_rn(__fsub_rn(wc, wmin), scale));
        float q = __fadd_rn(__fmul_rn(kf, scale), wmin);
        double ed = (double)q - (double)wmin - (double)scale * (double)kf;
        e = (float)ed;
    }
    kq[i] = __float2bfloat16_rn(kf);
    eq[i] = __float2bfloat16_rn(e);
}

// ---------------- x: [B,T,IN] -> [T,B,IN]/15 (fp32, R6-identical) ----------
__global__ void prep_x_kernel(const float* __restrict__ x, float* __restrict__ xs) {
    int idx = blockIdx.x * blockDim.x + threadIdx.x;
    if (idx >= TB_ * IN_) return;
    int i  = idx % IN_;
    int rb = idx / IN_;
    int b  = rb % B_;
    int t  = rb / B_;
    xs[idx] = __fdiv_rn(x[((size_t)b * T_ + t) * IN_ + i], 15.0f);
}

// ---------------- rowsum of bf16 spikes (exact integers) -------------------
__global__ void rowsum_b_kernel(const __nv_bfloat16* __restrict__ S, float* __restrict__ R) {
    int w = (blockIdx.x * blockDim.x + threadIdx.x) >> 5;
    int l = threadIdx.x & 31;
    if (w >= TB_) return;
    const uint4* p = (const uint4*)(S + (size_t)w * H_);
    float s = 0.0f;
#pragma unroll
    for (int i = 0; i < 4; i++) {
        uint4 v = p[l + i * 32];
        const __nv_bfloat16* h = (const __nv_bfloat16*)&v;
#pragma unroll
        for (int c = 0; c < 8; c++) s += __bfloat162float(h[c]);
    }
#pragma unroll
    for (int o = 16; o; o >>= 1) s += __shfl_xor_sync(0xffffffffu, s, o);
    if (l == 0) R[w] = s;
}

// ---------------- LIF scans ------------------------------------------------
// Layer 1: direct fp32 currents (R6-identical)
__global__ void lif_sub1_kernel(const float* __restrict__ cur, float* __restrict__ spk,
                                __nv_bfloat16* __restrict__ spkb, float beta, int n) {
    int idx = blockIdx.x * blockDim.x + threadIdx.x;
    if (idx >= n) return;
    float m = 0.0f;
    for (int t = 0; t < T_; t++) {
        float c     = cur[(size_t)t * n + idx];
        float reset = (m > 1.0f) ? 1.0f : 0.0f;
        float base  = __fadd_rn(__fmul_rn(beta, m), c);
        m = base - reset;
        float s = (m > 1.0f) ? 1.0f : 0.0f;
        spk[(size_t)t * n + idx]  = s;
        spkb[(size_t)t * n + idx] = __float2bfloat16_rn(s);
    }
}

// Hidden layers: c = D + wmin*R (D already = scale*Dk + De from fused epilogue)
__global__ void lif_sub_kernel(const float* __restrict__ D, const float* __restrict__ R,
                               float* __restrict__ spk, __nv_bfloat16* __restrict__ spkb,
                               float beta, float wmin) {
    int idx = blockIdx.x * blockDim.x + threadIdx.x;
    if (idx >= B_ * H_) return;
    int b = idx / H_, h = idx % H_;
    float m = 0.0f;
    for (int t = 0; t < T_; t++) {
        size_t mm = (size_t)t * B_ + b;
        float c = fmaf(wmin, R[mm], D[mm * H_ + h]);
        float reset = (m > 1.0f) ? 1.0f : 0.0f;
        float base  = __fadd_rn(__fmul_rn(beta, m), c);
        m = base - reset;
        float s = (m > 1.0f) ? 1.0f : 0.0f;
        spk[(size_t)t * (B_ * H_) + idx]  = s;
        spkb[(size_t)t * (B_ * H_) + idx] = __float2bfloat16_rn(s);
    }
}

__global__ void lif_zero_kernel(const float* __restrict__ D, const float* __restrict__ R,
                                float* __restrict__ spk, float* __restrict__ mem,
                                float beta, float wmin) {
    int idx = blockIdx.x * blockDim.x + threadIdx.x;
    if (idx >= B_ * OUT_) return;
    int b = idx / OUT_, h = idx % OUT_;
    float m = 0.0f;
    for (int t = 0; t < T_; t++) {
        size_t mm = (size_t)t * B_ + b;
        float c = fmaf(wmin, R[mm], D[mm * 128 + h]);
        bool  rst  = (m > 1.0f);
        float base = __fadd_rn(__fmul_rn(beta, m), c);
        m = rst ? 0.0f : base;
        spk[(size_t)t * (B_ * OUT_) + idx] = (m > 1.0f) ? 1.0f : 0.0f;
        mem[(size_t)t * (B_ * OUT_) + idx] = m;
    }
}

// ---------------------------------------------------------------------------
extern "C" void kernel_launch(void* const* d_in, const int* in_sizes, int n_in,
                              void* d_out, int out_size) {
    const float* x  = (const float*)d_in[0];
    const float* w1 = (const float*)d_in[1];
    const float* w2 = (const float*)d_in[2];
    const float* w3 = (const float*)d_in[3];
    const float* w4 = (const float*)d_in[4];
    float* out = (float*)d_out;

    float *xs, *q1, *cur, *R;
    __nv_bfloat16 *w2k, *w2e, *w3k, *w3e, *w4k, *w4e, *spkb;
    cudaGetSymbolAddress((void**)&xs, g_xs);   cudaGetSymbolAddress((void**)&q1, g_q1);
    cudaGetSymbolAddress((void**)&w2k, g_w2k); cudaGetSymbolAddress((void**)&w2e, g_w2e);
    cudaGetSymbolAddress((void**)&w3k, g_w3k); cudaGetSymbolAddress((void**)&w3e, g_w3e);
    cudaGetSymbolAddress((void**)&w4k, g_w4k); cudaGetSymbolAddress((void**)&w4e, g_w4e);
    cudaGetSymbolAddress((void**)&cur, g_cur);
    cudaGetSymbolAddress((void**)&spkb, g_spkb);
    cudaGetSymbolAddress((void**)&R, g_R);

    const size_t SPK  = (size_t)TB_ * H_;
    const size_t SPK4 = (size_t)TB_ * OUT_;
    float* spk1 = out;
    float* spk2 = out + SPK;
    float* spk3 = out + 2 * SPK;
    float* spk4 = out + 3 * SPK;
    float* mem4 = out + 3 * SPK + SPK4;

    const float scale1 = (float)((0.5 - (-0.5)) / 15.0);
    const float scale2 = (float)((1.0 - 0.001) / 15.0);

    const int SMEM = 3 * 32768;   // 98304 (3-stage)
    cudaFuncSetAttribute(gemm_dual, cudaFuncAttributeMaxDynamicSharedMemorySize, SMEM);

    // ---- prep
    quant_kernel<<<(H_ * IN_ + 255) / 256, 256>>>(w1, q1, H_ * IN_, -0.5f, 0.5f, scale1);
    quantke_kernel<<<(H_ * H_ + 255) / 256, 256>>>(w2, w2k, w2e, H_ * H_, H_ * H_, 0.001f, 1.0f, scale2);
    quantke_kernel<<<(H_ * H_ + 255) / 256, 256>>>(w3, w3k, w3e, H_ * H_, H_ * H_, 0.001f, 1.0f, scale2);
    quantke_kernel<<<(128 * H_ + 255) / 256, 256>>>(w4, w4k, w4e, 128 * H_, OUT_ * H_, 0.001f, 1.0f, scale2);
    prep_x_kernel<<<(TB_ * IN_ + 255) / 256, 256>>>(x, xs);

    dim3 gL1(H_ / 128, TB_ / 128);    // (8, 200) fp32 L1
    dim3 gHid(H_ / 64, TB_ / 128);    // (16, 200) hidden dual
    dim3 gOut(2, TB_ / 128);          // (2, 200)  L4 (N padded 128)
    const int RS_BLK = (TB_ * 32 + 255) / 256;

    // ---- Layer 1 (fp32, proven path — DO NOT TOUCH)
    gemm_nt_kernel<<<gL1, 256>>>(xs, q1, cur, TB_, H_, IN_);
    lif_sub1_kernel<<<(B_ * H_ + 255) / 256, 256>>>(cur, spk1, spkb, 0.9f, B_ * H_);

    // ---- Layer 2 (fused k+e dual GEMM, exact)
    rowsum_b_kernel<<<RS_BLK, 256>>>(spkb, R);
    gemm_dual<<<gHid, 256, SMEM>>>(spkb, w2k, w2e, cur, H_, H_, scale2);
    lif_sub_kernel<<<(B_ * H_ + 255) / 256, 256>>>(cur, R, spk2, spkb, 0.85f, 0.001f);

    // ---- Layer 3
    rowsum_b_kernel<<<RS_BLK, 256>>>(spkb, R);
    gemm_dual<<<gHid, 256, SMEM>>>(spkb, w3k, w3e, cur, H_, H_, scale2);
    lif_sub_kernel<<<(B_ * H_ + 255) / 256, 256>>>(cur, R, spk3, spkb, 0.8f, 0.001f);

    // ---- Layer 4 (N padded to 128)
    rowsum_b_kernel<<<RS_BLK, 256>>>(spkb, R);
    gemm_dual<<<gOut, 256, SMEM>>>(spkb, w4k, w4e, cur, 128, H_, scale2);
    lif_zero_kernel<<<(B_ * OUT_ + 255) / 256, 256>>>(cur, R, spk4, mem4, 0.95f, 0.001f);

    (void)in_sizes; (void)n_in; (void)out_size;
}